// round 4
// baseline (speedup 1.0000x reference)
#include <cuda_runtime.h>

#define BB 16
#define SS 4096
#define HH 1024
#define QD 1024
#define KD 2048

#define NCHUNK 32                     // value chunks per batch
#define CROWS  128                    // rows per value chunk
#define IROWS  32                     // rows per score item
#define N_SITEMS (BB * SS / IROWS)    // 2048
#define N_VITEMS (BB * NCHUNK * 2)    // 1024 (2 k-blocks of 1024 cols)
#define TOTAL_ITEMS (N_SITEMS + N_VITEMS)
#define LEAD   256
#define NG     ((N_SITEMS - LEAD) / 2)   // 896 interleave groups
#define Q1     (NG * 3)                  // 2688

// Scratch (no allocation allowed anywhere)
__device__ float g_q[BB * HH];
__device__ float g_escore[BB * SS];          // unnormalized exp(score), 0 if masked
__device__ float g_isum[N_SITEMS];           // per-item partial sums (fixed-order reduce later)
__device__ float g_partial[NCHUNK * BB * KD];
__device__ int   g_flag[BB * NCHUNK];        // 512 chunk-completion counters (0..4)
__device__ int   g_work;

// tanh via MUFU.EX2 + MUFU.RCP: abs err ~1e-7
__device__ __forceinline__ float fast_tanh(float x) {
    float e = __expf(2.0f * x);
    return 1.0f - __fdividef(2.0f, e + 1.0f);
}

// ---------------------------------------------------------------------------
// K1: q[b,h] = query[b,:]·Wq[h,:]  (warp per output).  Also resets queue state.
// ---------------------------------------------------------------------------
__global__ void k1_proj(const float* __restrict__ query, const float* __restrict__ Wq) {
    if (blockIdx.x == 0) {                 // reset for this replay (k_fused runs after)
        g_flag[threadIdx.x] = 0;
        g_flag[threadIdx.x + 256] = 0;
        if (threadIdx.x == 0) g_work = 0;
    }
    int warp = (blockIdx.x * blockDim.x + threadIdx.x) >> 5;
    int lane = threadIdx.x & 31;
    if (warp >= BB * HH) return;
    int b = warp >> 10;
    int h = warp & (HH - 1);
    const float4* q4 = (const float4*)(query + (size_t)b * QD);
    const float4* w4 = (const float4*)(Wq + (size_t)h * QD);
    float acc = 0.f;
#pragma unroll
    for (int i = 0; i < QD / 128; i++) {
        float4 a = q4[lane + i * 32];
        float4 w = w4[lane + i * 32];
        acc += a.x * w.x + a.y * w.y + a.z * w.z + a.w * w.w;
    }
#pragma unroll
    for (int o = 16; o; o >>= 1) acc += __shfl_xor_sync(0xffffffffu, acc, o);
    if (lane == 0) g_q[warp] = acc;
}

// ---------------------------------------------------------------------------
// Fused persistent kernel: score items (proj_key stream + tanh + exp) and
// value items (value stream weighted by escore) pulled from one interleaved
// queue so both HBM streams overlap.
// ---------------------------------------------------------------------------
__global__ void __launch_bounds__(256) k_fused(const float* __restrict__ pk,
                                               const float* __restrict__ w_energy,
                                               const int*   __restrict__ mask,
                                               const float* __restrict__ value) {
    __shared__ float sh[CROWS];
    __shared__ int sh_item;
    int tid = threadIdx.x, lane = tid & 31, wid = tid >> 5;

    for (;;) {
        if (tid == 0) sh_item = atomicAdd(&g_work, 1);
        __syncthreads();
        int p = sh_item;
        if (p >= TOTAL_ITEMS) return;

        // --- map pop index -> item (score lead, then 2 score : 1 value) ---
        int sitem = -1, vitem = -1;
        if (p < LEAD) sitem = p;
        else {
            int q = p - LEAD;
            if (q < Q1) { int g = q / 3, r = q - g * 3;
                          if (r < 2) sitem = LEAD + g * 2 + r; else vitem = g; }
            else vitem = NG + (q - Q1);
        }

        if (sitem >= 0) {
            // ========== score item: 32 rows, 4 rows per warp ==========
            int r0 = sitem * IROWS;
            int b  = r0 >> 12;                          // / SS
            const float4* q4 = (const float4*)(g_q + (size_t)b * HH);
            const float4* w4 = (const float4*)w_energy;
#pragma unroll
            for (int j = 0; j < 4; j++) {
                int row = r0 + wid * 4 + j;
                const float4* p4 = (const float4*)(pk + (size_t)row * HH);
                float acc = 0.f;
#pragma unroll
                for (int i = 0; i < HH / 128; i++) {
                    float4 P = __ldcs(&p4[lane + i * 32]);
                    float4 Q = q4[lane + i * 32];
                    float4 W = w4[lane + i * 32];
                    acc += W.x * fast_tanh(Q.x + P.x);
                    acc += W.y * fast_tanh(Q.y + P.y);
                    acc += W.z * fast_tanh(Q.z + P.z);
                    acc += W.w * fast_tanh(Q.w + P.w);
                }
#pragma unroll
                for (int o = 16; o; o >>= 1) acc += __shfl_xor_sync(0xffffffffu, acc, o);
                if (lane == 0) {
                    float e = (mask[row] == 0) ? 0.f : __expf(fminf(acc, 80.f));
                    g_escore[row] = e;
                    sh[wid * 4 + j] = e;
                }
            }
            __syncthreads();
            if (tid < 32) {                             // fixed-order item sum
                float s = sh[tid];
#pragma unroll
                for (int o = 16; o; o >>= 1) s += __shfl_xor_sync(0xffffffffu, s, o);
                if (tid == 0) g_isum[sitem] = s;
            }
            __threadfence();                            // release (all threads)
            __syncthreads();
            if (tid == 0) atomicAdd(&g_flag[sitem >> 2], 1);
        } else {
            // ========== value item: 128 rows x 1024 cols ==========
            int c    = vitem >> 1;
            int b    = c >> 5;
            int ssec = c & 31;
            int kb   = vitem & 1;
            if (tid == 0) {
                while (((volatile int*)g_flag)[c] < 4) __nanosleep(40);
            }
            __syncthreads();
            __threadfence();                            // acquire (all threads)
            int s0 = ssec * CROWS;
            if (tid < CROWS) sh[tid] = g_escore[b * SS + s0 + tid];
            __syncthreads();

            int k4i = kb * 256 + tid;
            const float4* vp = (const float4*)(value + ((size_t)b * SS + s0) * KD) + k4i;
            float4 acc = make_float4(0.f, 0.f, 0.f, 0.f);
#pragma unroll 8
            for (int s = 0; s < CROWS; s++) {
                float4 v = __ldcs(&vp[(size_t)s * (KD / 4)]);
                float al = sh[s];
                acc.x += al * v.x;
                acc.y += al * v.y;
                acc.z += al * v.z;
                acc.w += al * v.w;
            }
            ((float4*)(g_partial + ((size_t)ssec * BB + b) * KD))[k4i] = acc;
        }
        __syncthreads();   // protect sh[] before next pop
    }
}

// ---------------------------------------------------------------------------
// Epilogue: per-batch sum (fixed order), normalize alphas + reduce ctx partials
// ---------------------------------------------------------------------------
__global__ void k_fin(float* __restrict__ ctx, float* __restrict__ alphas) {
    int b = blockIdx.x, tid = threadIdx.x, lane = tid & 31, wid = tid >> 5;
    __shared__ float red[8];
    __shared__ float s_inv;

    float s = (tid < 128) ? g_isum[b * 128 + tid] : 0.f;
#pragma unroll
    for (int o = 16; o; o >>= 1) s += __shfl_xor_sync(0xffffffffu, s, o);
    if (lane == 0) red[wid] = s;
    __syncthreads();
    if (tid == 0) {
        float t = 0.f;
#pragma unroll
        for (int i = 0; i < 8; i++) t += red[i];       // fixed order
        s_inv = 1.0f / t;
    }
    __syncthreads();
    float inv = s_inv;

#pragma unroll
    for (int i = 0; i < SS / 256; i++) {
        int sidx = b * SS + tid + i * 256;
        alphas[sidx] = g_escore[sidx] * inv;
    }
#pragma unroll
    for (int i = 0; i < KD / 256; i++) {
        int k = tid + i * 256;
        float acc = 0.f;
#pragma unroll
        for (int ssec = 0; ssec < NCHUNK; ssec++)       // fixed order
            acc += g_partial[((size_t)ssec * BB + b) * KD + k];
        ctx[b * KD + k] = acc * inv;
    }
}

extern "C" void kernel_launch(void* const* d_in, const int* in_sizes, int n_in,
                              void* d_out, int out_size) {
    const int*   mask     = (const int*)d_in[0];
    const float* query    = (const float*)d_in[1];
    const float* proj_key = (const float*)d_in[2];
    const float* value    = (const float*)d_in[3];
    const float* Wq       = (const float*)d_in[4];
    const float* w_energy = (const float*)d_in[5];

    float* out    = (float*)d_out;
    float* ctx    = out;              // (B,1,K) = 32768 floats
    float* alphas = out + BB * KD;    // (B,1,S) = 65536 floats

    k1_proj<<<BB * HH / 8, 256>>>(query, Wq);
    k_fused<<<1184, 256>>>(proj_key, w_energy, mask, value);
    k_fin<<<BB, 256>>>(ctx, alphas);
}

// round 6
// speedup vs baseline: 1.1506x; 1.1506x over previous
#include <cuda_runtime.h>

#define BB 16
#define SS 4096
#define HH 1024
#define QD 1024
#define KD 2048
#define SSPLIT 32
#define SCHUNK (SS / SSPLIT)   // 128

// Scratch (no allocation allowed in kernel_launch)
__device__ float g_q[BB * HH];                 // 64 KB
__device__ float g_scores[BB * SS];            // 256 KB
__device__ float g_partial[SSPLIT * BB * KD];  // 4 MB

// tanh via MUFU.EX2 + MUFU.RCP: abs err ~1e-7, saturates correctly at +/-inf
__device__ __forceinline__ float fast_tanh(float x) {
    float e = __expf(2.0f * x);
    return 1.0f - __fdividef(2.0f, e + 1.0f);
}

// ---------------------------------------------------------------------------
// K1: q[b,h] = sum_q query[b,q] * Wq[h,q]
// Warp computes a 2h x 16b tile over the full q-dim: Wq is read ONCE from
// DRAM (4 MB), query (64 KB) hits L2. 512 warps total.
// ---------------------------------------------------------------------------
__global__ void __launch_bounds__(256) k1_proj(const float* __restrict__ query,
                                               const float* __restrict__ Wq) {
    int warp = (blockIdx.x * blockDim.x + threadIdx.x) >> 5;  // 0..511
    int lane = threadIdx.x & 31;
    int h0 = warp * 2;

    const float4* w40 = (const float4*)(Wq + (size_t)h0 * QD);
    const float4* w41 = (const float4*)(Wq + (size_t)(h0 + 1) * QD);
    const float4* q4  = (const float4*)query;

    float acc0[BB], acc1[BB];
#pragma unroll
    for (int b = 0; b < BB; b++) { acc0[b] = 0.f; acc1[b] = 0.f; }

#pragma unroll
    for (int i = 0; i < QD / 128; i++) {
        float4 w0 = w40[lane + i * 32];
        float4 w1 = w41[lane + i * 32];
#pragma unroll
        for (int b = 0; b < BB; b++) {
            float4 q = q4[b * (QD / 4) + lane + i * 32];
            acc0[b] += w0.x * q.x + w0.y * q.y + w0.z * q.z + w0.w * q.w;
            acc1[b] += w1.x * q.x + w1.y * q.y + w1.z * q.z + w1.w * q.w;
        }
    }
#pragma unroll
    for (int b = 0; b < BB; b++) {
#pragma unroll
        for (int o = 16; o; o >>= 1) {
            acc0[b] += __shfl_xor_sync(0xffffffffu, acc0[b], o);
            acc1[b] += __shfl_xor_sync(0xffffffffu, acc1[b], o);
        }
    }
    if (lane == 0) {
#pragma unroll
        for (int b = 0; b < BB; b++) {
            g_q[b * HH + h0]     = acc0[b];
            g_q[b * HH + h0 + 1] = acc1[b];
        }
    }
}

// ---------------------------------------------------------------------------
// K2: scores[b,s] = sum_h w[h] * tanh(q[b,h] + pk[b,s,h])   (warp per row)
// Streams 256 MB of proj_key (ldcs); q and w_energy hit L2.
// ---------------------------------------------------------------------------
__global__ void k2_scores(const float* __restrict__ pk, const float* __restrict__ w_energy) {
    int warp = (blockIdx.x * blockDim.x + threadIdx.x) >> 5;  // == b*SS + s
    int lane = threadIdx.x & 31;
    int b = warp >> 12;  // / SS
    const float4* p4 = (const float4*)(pk + (size_t)warp * HH);
    const float4* q4 = (const float4*)(g_q + (size_t)b * HH);
    const float4* w4 = (const float4*)w_energy;
    float acc = 0.f;
#pragma unroll
    for (int i = 0; i < HH / 128; i++) {
        float4 p = __ldcs(&p4[lane + i * 32]);
        float4 q = q4[lane + i * 32];
        float4 w = w4[lane + i * 32];
        acc += w.x * fast_tanh(q.x + p.x);
        acc += w.y * fast_tanh(q.y + p.y);
        acc += w.z * fast_tanh(q.z + p.z);
        acc += w.w * fast_tanh(q.w + p.w);
    }
#pragma unroll
    for (int o = 16; o; o >>= 1) acc += __shfl_xor_sync(0xffffffffu, acc, o);
    if (lane == 0) g_scores[warp] = acc;
}

// ---------------------------------------------------------------------------
// K3: masked softmax over S per batch. One block (1024 thr) per b.
// alphas written directly into d_out (offset BB*KD).
// ---------------------------------------------------------------------------
__global__ void k3_softmax(const int* __restrict__ mask, float* __restrict__ alphas) {
    int b = blockIdx.x;
    int tid = threadIdx.x;
    int lane = tid & 31, wid = tid >> 5;
    __shared__ float red[32];
    __shared__ float bcast;

    float v[4];
    float mx = -INFINITY;
#pragma unroll
    for (int i = 0; i < 4; i++) {
        int s = tid + i * 1024;
        float sc = g_scores[b * SS + s];
        v[i] = (mask[b * SS + s] == 0) ? -INFINITY : sc;
        mx = fmaxf(mx, v[i]);
    }
#pragma unroll
    for (int o = 16; o; o >>= 1) mx = fmaxf(mx, __shfl_xor_sync(0xffffffffu, mx, o));
    if (lane == 0) red[wid] = mx;
    __syncthreads();
    if (tid < 32) {
        float m = red[tid];
#pragma unroll
        for (int o = 16; o; o >>= 1) m = fmaxf(m, __shfl_xor_sync(0xffffffffu, m, o));
        if (tid == 0) bcast = m;
    }
    __syncthreads();
    mx = bcast;

    float e[4];
    float sum = 0.f;
#pragma unroll
    for (int i = 0; i < 4; i++) {
        e[i] = __expf(v[i] - mx);   // exp(-inf) == 0 handles mask
        sum += e[i];
    }
    __syncthreads();  // red reuse
#pragma unroll
    for (int o = 16; o; o >>= 1) sum += __shfl_xor_sync(0xffffffffu, sum, o);
    if (lane == 0) red[wid] = sum;
    __syncthreads();
    if (tid < 32) {
        float m = red[tid];
#pragma unroll
        for (int o = 16; o; o >>= 1) m += __shfl_xor_sync(0xffffffffu, m, o);
        if (tid == 0) bcast = m;
    }
    __syncthreads();
    float inv = 1.0f / bcast;
#pragma unroll
    for (int i = 0; i < 4; i++) {
        int s = tid + i * 1024;
        alphas[b * SS + s] = e[i] * inv;
    }
}

// ---------------------------------------------------------------------------
// K4: partial context, float4 wide. grid = (KD/1024, BB, SSPLIT) = 1024 blocks.
// Each thread owns 4 k-columns; streams 512 MB of value (ldcs) at high MLP.
// ---------------------------------------------------------------------------
__global__ void __launch_bounds__(256) k4_ctx(const float* __restrict__ value,
                                              const float* __restrict__ alphas) {
    __shared__ float a[SCHUNK];
    int b = blockIdx.y;
    int ssec = blockIdx.z;
    int k4i = blockIdx.x * blockDim.x + threadIdx.x;  // float4 column index
    int s0 = ssec * SCHUNK;

    if (threadIdx.x < SCHUNK)
        a[threadIdx.x] = alphas[b * SS + s0 + threadIdx.x];
    __syncthreads();

    const float4* vp = (const float4*)(value + ((size_t)b * SS + s0) * KD) + k4i;
    float4 acc = make_float4(0.f, 0.f, 0.f, 0.f);
#pragma unroll 8
    for (int s = 0; s < SCHUNK; s++) {
        float4 v = __ldcs(&vp[(size_t)s * (KD / 4)]);
        float al = a[s];
        acc.x += al * v.x;
        acc.y += al * v.y;
        acc.z += al * v.z;
        acc.w += al * v.w;
    }

    float4* pp = (float4*)(g_partial + ((size_t)ssec * BB + b) * KD) + k4i;
    *pp = acc;
}

// ---------------------------------------------------------------------------
// K5: reduce SSPLIT partials -> context (fixed order => deterministic)
// ---------------------------------------------------------------------------
__global__ void k5_reduce(float* __restrict__ ctx) {
    int i = blockIdx.x * blockDim.x + threadIdx.x;  // float4 index, 0 .. BB*KD/4-1
    const float4* p = (const float4*)g_partial;
    float4 acc = make_float4(0.f, 0.f, 0.f, 0.f);
#pragma unroll
    for (int j = 0; j < SSPLIT; j++) {
        float4 v = p[(size_t)j * (BB * KD / 4) + i];
        acc.x += v.x; acc.y += v.y; acc.z += v.z; acc.w += v.w;
    }
    ((float4*)ctx)[i] = acc;
}

extern "C" void kernel_launch(void* const* d_in, const int* in_sizes, int n_in,
                              void* d_out, int out_size) {
    const int*   mask     = (const int*)d_in[0];
    const float* query    = (const float*)d_in[1];
    const float* proj_key = (const float*)d_in[2];
    const float* value    = (const float*)d_in[3];
    const float* Wq       = (const float*)d_in[4];
    const float* w_energy = (const float*)d_in[5];

    float* out    = (float*)d_out;
    float* ctx    = out;              // (B,1,K) = 32768 floats
    float* alphas = out + BB * KD;    // (B,1,S) = 65536 floats

    k1_proj<<<64, 256>>>(query, Wq);                      // 512 warps, 2h x 16b tiles
    k2_scores<<<BB * SS / 8, 256>>>(proj_key, w_energy);
    k3_softmax<<<BB, 1024>>>(mask, alphas);
    k4_ctx<<<dim3(KD / 1024, BB, SSPLIT), 256>>>(value, alphas);
    k5_reduce<<<BB * KD / 4 / 256, 256>>>(ctx);
}